// round 11
// baseline (speedup 1.0000x reference)
#include <cuda_runtime.h>
#include <math.h>
#include <stdint.h>

#define Bn 64
#define Pn 25200
#define Gn 48
#define NB3 99            // ceil(Pn/256)
#define NTH 256
#define NTHM 1024         // merged loss+select kernel threads
#define KPT 25            // priors per thread in merged kernel (25*1024 >= 25200)
#define NPREP1 NB3                // prior-prep blocks
#define NPREP2 ((Bn*Gn + NTH - 1)/NTH)  // gt-prep blocks (12)

// ---------------- scratch (no allocations allowed) ----------------
__device__ float4 d_pf4[Pn];                 // priors point form
__device__ float4 d_truths4[Bn*Gn];          // scaled gt boxes (corner form)
__device__ float  d_areas[Bn*Gn];            // gt areas
__device__ float  d_lms[Bn*Gn*10];           // scaled landmarks
__device__ int    d_labels[Bn*Gn];           // label after 0->1 and landm<0 -> -1
__device__ unsigned long long d_gpart[Bn*Gn*NB3]; // per-(b,g,chunk) partial argmax keys
__device__ unsigned d_bpi[Bn*Gn];            // best prior index per gt
__device__ unsigned long long d_vmask[Bn];   // valid-gt bitmask per batch
__device__ unsigned long long d_cmask[Bn*NB3]; // per-(batch,chunk) gt-index mask
__device__ float2 d_povg[Bn*Pn];             // per-prior (exact ov, bg as int bits)
__device__ int    d_hv[Bn];                  // has_valid per batch
__device__ double d_b_ll[Bn], d_b_lm[Bn], d_b_lc[Bn];
__device__ int    d_b_np[Bn], d_b_np1[Bn];

// ---------------- helpers ----------------
__device__ __forceinline__ float sl1(float d) {
    d = fabsf(d);
    return d < 1.0f ? 0.5f * d * d : d - 0.5f;
}

__device__ __forceinline__ float inter_fn(float4 t, float4 pf) {
    float ltx = fmaxf(t.x, pf.x), lty = fmaxf(t.y, pf.y);
    float rbx = fminf(t.z, pf.z), rby = fminf(t.w, pf.w);
    float iw = fmaxf(rbx - ltx, 0.0f), ih = fmaxf(rby - lty, 0.0f);
    return iw * ih;
}

// ---------------- K0: fused prep (priors point form + gt scaling) ----------------
__global__ void k_prep(const float* __restrict__ priors,
                       const float* __restrict__ gtb, const int* __restrict__ gtl,
                       const float* __restrict__ gtlm, const int* __restrict__ img) {
    if (blockIdx.x < NPREP1) {
        int i = blockIdx.x * NTH + threadIdx.x;
        if (i < Pn) {
            float4 pr = ((const float4*)priors)[i];
            float hx = pr.z * 0.5f, hy = pr.w * 0.5f;
            float4 pf;
            pf.x = pr.x - hx; pf.y = pr.y - hy;
            pf.z = pr.x + hx; pf.w = pr.y + hy;
            d_pf4[i] = pf;
        }
    } else {
        int i = (blockIdx.x - NPREP1) * NTH + threadIdx.x;
        if (i < Bn * Gn) {
            int b = i / Gn;
            float w = (float)img[b * 2 + 1];
            float h = (float)img[b * 2 + 0];
            float x1 = gtb[i*4+0] / w, y1 = gtb[i*4+1] / h;
            float x2 = gtb[i*4+2] / w, y2 = gtb[i*4+3] / h;
            float4 t; t.x = x1; t.y = y1; t.z = x2; t.w = y2;
            d_truths4[i] = t;
            d_areas[i] = (x2 - x1) * (y2 - y1);
            float lm0 = 0.0f;
            #pragma unroll
            for (int j = 0; j < 10; j++) {
                float v = gtlm[i*10+j] / ((j & 1) ? h : w);
                d_lms[i*10+j] = v;
                if (j == 0) lm0 = v;
            }
            int lab = gtl[i];
            if (lab == 0) lab = 1;
            if (lm0 < 0.0f) lab = -1;
            d_labels[i] = lab;
        }
    }
}

// ---------------- KA: single-pass IoU, dual argmax ----------------
__global__ void k_A(const int* __restrict__ gnum_arr) {
    __shared__ float4 str[Gn];
    __shared__ float  sa[Gn];
    __shared__ unsigned long long swk[Gn][8];
    int b = blockIdx.y, chunk = blockIdx.x;
    int tid = threadIdx.x, lane = tid & 31, wid = tid >> 5;

    if (tid < Gn * 4) ((float*)str)[tid] = ((const float*)d_truths4)[b * Gn * 4 + tid];
    if (tid < Gn) sa[tid] = d_areas[b * Gn + tid];
    if (tid == 0) {
        d_cmask[b * NB3 + chunk] = 0ull;          // zeroed before B's atomicOr
        if (chunk == 0) { d_vmask[b] = 0ull; d_hv[b] = 0; }
    }
    __syncthreads();

    int gnum = min(gnum_arr[b], Gn);
    int p = chunk * NTH + tid;
    float4 pf;
    if (p < Pn) pf = d_pf4[p];
    else { pf.x = -1.0f; pf.y = -1.0f; pf.z = -1.0f; pf.w = -1.0f; }  // degenerate: inter=0
    float pa = (pf.z - pf.x) * (pf.w - pf.y);

    float bi = -1.0f, bd = 1.0f; int bg = 0;
    for (int g = 0; g < gnum; g++) {
        float in_ = inter_fn(str[g], pf);
        float c   = sa[g] + pa;
        float dn_ = c - in_;
        unsigned k32 = __float_as_uint(__fdividef(in_, dn_));
        if (in_ * bd > bi * dn_) { bi = in_; bd = dn_; bg = g; }
        unsigned mx = __reduce_max_sync(0xFFFFFFFFu, k32);
        unsigned bal = __ballot_sync(0xFFFFFFFFu, k32 == mx);
        if (lane == __ffs(bal) - 1)
            swk[g][wid] = ((unsigned long long)mx << 32) | (0xFFFFFFFFu - (unsigned)p);
    }
    __syncthreads();
    if (tid < Gn && tid < gnum) {
        unsigned long long best = swk[tid][0];
        #pragma unroll
        for (int w = 1; w < 8; w++) {
            unsigned long long o = swk[tid][w];
            if (o > best) best = o;
        }
        d_gpart[((size_t)b * Gn + tid) * NB3 + chunk] = best;
    }
    if (p < Pn) {
        float2 r; r.x = bi / bd; r.y = __int_as_float(bg);   // exact IEEE ov
        d_povg[(size_t)b * Pn + p] = r;
    }
}

// ---------------- KB: reduce per-g partials, emit fix-up tables ----------------
__global__ void k_B(const int* __restrict__ gnum_arr) {
    int idx = blockIdx.x * NTH + threadIdx.x;
    if (idx >= Bn * Gn) return;
    int b = idx / Gn, g = idx % Gn;
    if (g >= min(gnum_arr[b], Gn)) return;
    const unsigned long long* row = &d_gpart[(size_t)idx * NB3];
    unsigned long long best = row[0];
    for (int k = 1; k < NB3; k++) {
        unsigned long long v = row[k];
        if (v > best) best = v;
    }
    unsigned p = 0xFFFFFFFFu - (unsigned)best;
    d_bpi[idx] = p;
    atomicOr(&d_cmask[b * NB3 + (p / NTH)], 1ull << g);
    if ((unsigned)(best >> 32) >= 0x3E4CCCCDu) {          // iou >= 0.2f
        atomicOr(&d_vmask[b], 1ull << g);
        atomicOr(&d_hv[b], 1);
    }
}

// ---------------- KCB: merged losses + ce + hard-negative radix select ------------
// One block per batch. Each thread owns KPT=25 priors; ce lives in registers
// across the radix passes (no d_ce array at all).
__global__ void __launch_bounds__(NTHM, 1) k_cb(
        const float* __restrict__ loc, const float* __restrict__ conf,
        const float* __restrict__ lmd, const float* __restrict__ priors) {
    int b = blockIdx.x, tid = threadIdx.x;
    int lane = tid & 31, wid = tid >> 5;
    __shared__ float4 str[Gn];
    __shared__ float  slm[Gn * 10];
    __shared__ int    slab[Gn];
    __shared__ unsigned sbpi[Gn];
    __shared__ unsigned long long scm[NB3];
    __shared__ double sdw[32];
    __shared__ int    siw[32];
    __shared__ int    hist[256];
    __shared__ unsigned s_prefix;
    __shared__ int s_rem;
    __shared__ double s_ll, s_lm, s_pce;
    __shared__ int s_np, s_np1;

    if (tid < Gn * 4) ((float*)str)[tid] = ((const float*)d_truths4)[b * Gn * 4 + tid];
    if (tid < Gn * 10) slm[tid] = d_lms[b * Gn * 10 + tid];
    if (tid < Gn) { slab[tid] = d_labels[b * Gn + tid]; sbpi[tid] = d_bpi[b * Gn + tid]; }
    if (tid < NB3) scm[tid] = d_cmask[b * NB3 + tid];
    if (tid < 256) hist[tid] = 0;
    __syncthreads();
    int hv = d_hv[b];
    unsigned long long vm = d_vmask[b];
    long long base = (long long)b * Pn;

    float ce_r[KPT];                 // -1 => pos or OOB; >=0 => hard-neg candidate
    float ll = 0.0f, llm = 0.0f, pce = 0.0f;
    int np = 0, np1 = 0;

    #pragma unroll
    for (int k = 0; k < KPT; k++) {
        int p = tid + k * NTHM;
        ce_r[k] = -1.0f;
        if (p < Pn) {
            float2 og = d_povg[base + p];
            float ov = og.x;
            int bg = __float_as_int(og.y);
            unsigned long long cm = scm[p >> 8];
            while (cm) {
                int j = __ffsll((long long)cm) - 1;   // ascending j => later j wins
                cm &= cm - 1;
                if (sbpi[j] == (unsigned)p) {
                    bg = j;
                    if ((vm >> j) & 1ull) ov = 2.0f;
                }
            }
            int lab = slab[bg];
            int c = (hv && ov >= 0.35f) ? lab : 0;
            bool pos = (c != 0), pos1 = (c > 0);
            float2 cd = ((const float2*)conf)[base + p];
            float m = fmaxf(cd.x, cd.y);
            float logz = m + logf(expf(cd.x - m) + expf(cd.y - m));
            float ce = logz - (pos ? cd.y : cd.x);
            if (pos) {
                np++; pce += ce;
                float4 pr = ((const float4*)priors)[p];
                float4 t = str[bg];
                float s0 = 0.1f * pr.z, s1 = 0.1f * pr.w;
                float tx = ((t.x + t.z) * 0.5f - pr.x) / s0;
                float ty = ((t.y + t.w) * 0.5f - pr.y) / s1;
                float tw = logf((t.z - t.x) / pr.z) / 0.2f;
                float th = logf((t.w - t.y) / pr.w) / 0.2f;
                float4 lc = ((const float4*)loc)[base + p];
                ll += sl1(lc.x - tx) + sl1(lc.y - ty) + sl1(lc.z - tw) + sl1(lc.w - th);
                if (pos1) {
                    np1++;
                    const float2* lrow = (const float2*)(lmd + (base + p) * 10);
                    const float* tg = &slm[bg * 10];
                    #pragma unroll
                    for (int i = 0; i < 5; i++) {
                        float2 lv = lrow[i];
                        float ttx = (tg[2*i]   - pr.x) / s0;
                        float tty = (tg[2*i+1] - pr.y) / s1;
                        llm += sl1(lv.x - ttx) + sl1(lv.y - tty);
                    }
                }
            } else {
                ce_r[k] = ce;          // ce >= 0 always (logsumexp >= gathered)
            }
        }
    }

    // ---- block reductions (deterministic: warp shuffle -> smem -> thread0 serial) ----
    int npk = np | (np1 << 16);
    #pragma unroll
    for (int off = 16; off > 0; off >>= 1) {
        ll  += __shfl_down_sync(0xFFFFFFFFu, ll,  off);
        llm += __shfl_down_sync(0xFFFFFFFFu, llm, off);
        pce += __shfl_down_sync(0xFFFFFFFFu, pce, off);
        npk += __shfl_down_sync(0xFFFFFFFFu, npk, off);
    }
    if (lane == 0) { sdw[wid] = (double)ll; siw[wid] = npk; }
    __syncthreads();
    if (tid == 0) {
        double a = 0; int e = 0;
        for (int i = 0; i < 32; i++) { a += sdw[i]; e += siw[i]; }
        s_ll = a; s_np = e & 0xFFFF; s_np1 = e >> 16;
    }
    __syncthreads();
    if (lane == 0) sdw[wid] = (double)llm;
    __syncthreads();
    if (tid == 0) { double a = 0; for (int i = 0; i < 32; i++) a += sdw[i]; s_lm = a; }
    __syncthreads();
    if (lane == 0) sdw[wid] = (double)pce;
    __syncthreads();
    if (tid == 0) { double a = 0; for (int i = 0; i < 32; i++) a += sdw[i]; s_pce = a; }
    __syncthreads();

    int npb = s_np;
    int K = min(7 * npb, Pn - 1);
    int cntnon = Pn - npb;
    double negsum = 0.0;

    if (K > 0) {
        if (K >= cntnon) {
            double locs = 0.0;
            #pragma unroll
            for (int k = 0; k < KPT; k++) if (ce_r[k] >= 0.0f) locs += (double)ce_r[k];
            #pragma unroll
            for (int off = 16; off > 0; off >>= 1) locs += __shfl_down_sync(0xFFFFFFFFu, locs, off);
            if (lane == 0) sdw[wid] = locs;
            __syncthreads();
            if (tid == 0) { double a = 0; for (int i = 0; i < 32; i++) a += sdw[i]; negsum = a; }
        } else {
            if (tid == 0) { s_prefix = 0u; s_rem = K; }
            __syncthreads();
            for (int shift = 24; shift >= 0; shift -= 8) {
                unsigned mask = (shift == 24) ? 0u : (0xFFFFFFFFu << (shift + 8));
                unsigned pref = s_prefix;
                // fixed trip count; OOB/pos encoded as ce_r = -1 (warp-uniform collectives)
                #pragma unroll
                for (int k = 0; k < KPT; k++) {
                    float v = ce_r[k];
                    bool valid = false; unsigned bin = 0xFFFFFFFFu;
                    if (v >= 0.0f) {
                        unsigned u = __float_as_uint(v);
                        if ((u & mask) == pref) { valid = true; bin = (u >> shift) & 255u; }
                    }
                    unsigned mm = __match_any_sync(0xFFFFFFFFu, valid ? bin : 0xFFFFFFFFu);
                    if (valid && lane == (__ffs(mm) - 1))
                        atomicAdd(&hist[bin], __popc(mm));
                }
                __syncthreads();
                if (tid == 0) {
                    int rem = s_rem, cum = 0, chosen = 0;
                    for (int v = 255; v >= 0; v--) {
                        int c = hist[v];
                        if (cum + c >= rem) { chosen = v; s_rem = rem - cum; break; }
                        cum += c;
                    }
                    s_prefix = pref | ((unsigned)chosen << shift);
                }
                __syncthreads();
                if (tid < 256) hist[tid] = 0;
                __syncthreads();
            }
            unsigned T = s_prefix;
            int rem = s_rem;
            double locs = 0.0;
            #pragma unroll
            for (int k = 0; k < KPT; k++) {
                float v = ce_r[k];
                if (v >= 0.0f && __float_as_uint(v) > T) locs += (double)v;
            }
            #pragma unroll
            for (int off = 16; off > 0; off >>= 1) locs += __shfl_down_sync(0xFFFFFFFFu, locs, off);
            if (lane == 0) sdw[wid] = locs;
            __syncthreads();
            if (tid == 0) {
                double a = 0; for (int i = 0; i < 32; i++) a += sdw[i];
                negsum = a + (double)rem * (double)__uint_as_float(T);
            }
        }
    }
    if (tid == 0) {
        d_b_ll[b] = s_ll;
        d_b_lm[b] = s_lm;
        d_b_lc[b] = s_pce + negsum;
        d_b_np[b] = npb;
        d_b_np1[b] = s_np1;
    }
}

// ---------------- K6: final combine ----------------
__global__ void k_final(float* __restrict__ out) {
    __shared__ double s1[Bn], s2[Bn], s3[Bn];
    __shared__ int i1[Bn], i2[Bn];
    int t = threadIdx.x;
    s1[t] = d_b_ll[t]; s2[t] = d_b_lc[t]; s3[t] = d_b_lm[t];
    i1[t] = d_b_np[t]; i2[t] = d_b_np1[t];
    __syncthreads();
    for (int s = Bn/2; s > 0; s >>= 1) {
        if (t < s) {
            s1[t] += s1[t+s]; s2[t] += s2[t+s]; s3[t] += s3[t+s];
            i1[t] += i1[t+s]; i2[t] += i2[t+s];
        }
        __syncthreads();
    }
    if (t == 0) {
        double N  = (double)(i1[0] > 0 ? i1[0] : 1);
        double N1 = (double)(i2[0] > 0 ? i2[0] : 1);
        out[0] = (float)(s1[0] / N);
        out[1] = (float)(s2[0] / N);
        out[2] = (float)(s3[0] / N1);
    }
}

// ---------------- launcher ----------------
extern "C" void kernel_launch(void* const* d_in, const int* in_sizes, int n_in,
                              void* d_out, int out_size) {
    const float* loc    = (const float*)d_in[0];
    const float* conf   = (const float*)d_in[1];
    const float* lmd    = (const float*)d_in[2];
    const float* priors = (const float*)d_in[3];
    const float* gtb    = (const float*)d_in[4];
    const int*   gtl    = (const int*)d_in[5];
    const float* gtlm   = (const float*)d_in[6];
    const int*   gnum   = (const int*)d_in[7];
    const int*   img    = (const int*)d_in[8];
    float* out = (float*)d_out;

    k_prep<<<NPREP1 + NPREP2, NTH>>>(priors, gtb, gtl, gtlm, img);
    k_A<<<dim3(NB3, Bn), NTH>>>(gnum);
    k_B<<<(Bn * Gn + NTH - 1) / NTH, NTH>>>(gnum);
    k_cb<<<Bn, NTHM>>>(loc, conf, lmd, priors);
    k_final<<<1, Bn>>>(out);
}

// round 13
// speedup vs baseline: 1.1614x; 1.1614x over previous
#include <cuda_runtime.h>
#include <math.h>
#include <stdint.h>

#define Bn 64
#define Pn 25200
#define Gn 48
#define NB3 99            // ceil(Pn/256)
#define NTH 256
#define NTHB 1024         // k_batch threads
#define KPT 25            // ce values per thread in k_batch (25*1024 >= 25200)

// ---------------- scratch (no allocations allowed) ----------------
__device__ unsigned long long d_gpart[Bn*Gn*NB3]; // per-(b,g,chunk) partial argmax keys
__device__ unsigned d_bpi[Bn*Gn];            // best prior index per gt
__device__ unsigned long long d_vmask[Bn];   // valid-gt bitmask per batch
__device__ unsigned long long d_cmask[Bn*NB3]; // per-(batch,chunk) gt-index mask
__device__ float2 d_povg[Bn*Pn];             // per-prior (exact ov, bg as int bits)
__device__ float  d_ce[Bn*Pn];               // ce for non-pos, -1 for pos
__device__ int    d_hv[Bn];                  // has_valid per batch
__device__ float  d_part_ll[Bn*NB3];
__device__ float  d_part_lm[Bn*NB3];
__device__ float  d_part_pce[Bn*NB3];
__device__ int    d_part_np[Bn*NB3];         // np | (np1<<16)
__device__ double d_b_ll[Bn], d_b_lm[Bn], d_b_lc[Bn];
__device__ int    d_b_np[Bn], d_b_np1[Bn];

// ---------------- helpers ----------------
__device__ __forceinline__ float sl1(float d) {
    d = fabsf(d);
    return d < 1.0f ? 0.5f * d * d : d - 0.5f;
}

__device__ __forceinline__ float inter_fn(float4 t, float4 pf) {
    float ltx = fmaxf(t.x, pf.x), lty = fmaxf(t.y, pf.y);
    float rbx = fminf(t.z, pf.z), rby = fminf(t.w, pf.w);
    float iw = fmaxf(rbx - ltx, 0.0f), ih = fmaxf(rby - lty, 0.0f);
    return iw * ih;
}

// ---------------- KA: single-pass IoU, dual argmax (no prep kernel) --------------
// Each thread: its prior vs all gnum gts ONCE. Gt boxes scaled in smem-load phase.
__global__ void k_A(const int* __restrict__ gnum_arr, const float* __restrict__ priors,
                    const float* __restrict__ gtb, const int* __restrict__ img) {
    __shared__ float4 str[Gn];
    __shared__ float  sa[Gn];
    __shared__ unsigned long long swk[Gn][8];
    int b = blockIdx.y, chunk = blockIdx.x;
    int tid = threadIdx.x, lane = tid & 31, wid = tid >> 5;

    float w = (float)img[b * 2 + 1];
    float h = (float)img[b * 2 + 0];
    if (tid < Gn * 4)
        ((float*)str)[tid] = gtb[b * Gn * 4 + tid] / ((tid & 1) ? h : w);
    if (tid < Gn) {
        float x1 = gtb[b*Gn*4 + tid*4+0] / w, y1 = gtb[b*Gn*4 + tid*4+1] / h;
        float x2 = gtb[b*Gn*4 + tid*4+2] / w, y2 = gtb[b*Gn*4 + tid*4+3] / h;
        sa[tid] = (x2 - x1) * (y2 - y1);
    }
    if (tid == 0) {
        d_cmask[b * NB3 + chunk] = 0ull;          // zeroed before B's atomicOr
        if (chunk == 0) { d_vmask[b] = 0ull; d_hv[b] = 0; }
    }
    __syncthreads();

    int gnum = min(gnum_arr[b], Gn);
    int p = chunk * NTH + tid;
    float4 pf;
    if (p < Pn) {
        float4 pr = ((const float4*)priors)[p];
        float hx = pr.z * 0.5f, hy = pr.w * 0.5f;
        pf.x = pr.x - hx; pf.y = pr.y - hy;
        pf.z = pr.x + hx; pf.w = pr.y + hy;
    } else {
        pf.x = -1.0f; pf.y = -1.0f; pf.z = -1.0f; pf.w = -1.0f;  // degenerate: inter=0
    }
    float pa = (pf.z - pf.x) * (pf.w - pf.y);

    float bi = -1.0f, bd = 1.0f; int bg = 0;
    for (int g = 0; g < gnum; g++) {
        float in_ = inter_fn(str[g], pf);
        float dn_ = sa[g] + pa - in_;
        unsigned k32 = __float_as_uint(__fdividef(in_, dn_));
        if (in_ * bd > bi * dn_) { bi = in_; bd = dn_; bg = g; }
        unsigned mx = __reduce_max_sync(0xFFFFFFFFu, k32);
        unsigned bal = __ballot_sync(0xFFFFFFFFu, k32 == mx);
        if (lane == __ffs(bal) - 1)
            swk[g][wid] = ((unsigned long long)mx << 32) | (0xFFFFFFFFu - (unsigned)p);
    }
    __syncthreads();
    if (tid < Gn && tid < gnum) {
        unsigned long long best = swk[tid][0];
        #pragma unroll
        for (int w2 = 1; w2 < 8; w2++) {
            unsigned long long o = swk[tid][w2];
            if (o > best) best = o;
        }
        d_gpart[((size_t)b * Gn + tid) * NB3 + chunk] = best;
    }
    if (p < Pn) {
        float2 r; r.x = bi / bd; r.y = __int_as_float(bg);   // exact IEEE ov
        d_povg[(size_t)b * Pn + p] = r;
    }
}

// ---------------- KB: reduce per-g partials, emit fix-up tables ----------------
__global__ void k_B(const int* __restrict__ gnum_arr) {
    int idx = blockIdx.x * NTH + threadIdx.x;
    if (idx >= Bn * Gn) return;
    int b = idx / Gn, g = idx % Gn;
    if (g >= min(gnum_arr[b], Gn)) return;
    const unsigned long long* row = &d_gpart[(size_t)idx * NB3];
    unsigned long long best = row[0];
    for (int k = 1; k < NB3; k++) {
        unsigned long long v = row[k];
        if (v > best) best = v;
    }
    unsigned p = 0xFFFFFFFFu - (unsigned)best;
    d_bpi[idx] = p;
    atomicOr(&d_cmask[b * NB3 + (p / NTH)], 1ull << g);
    if ((unsigned)(best >> 32) >= 0x3E4CCCCDu) {          // iou >= 0.2f
        atomicOr(&d_vmask[b], 1ull << g);
        atomicOr(&d_hv[b], 1);
    }
}

// ---------------- KC: losses + ce (full-grid; no IoU work) ----------------
__global__ void k_C(const float* __restrict__ loc, const float* __restrict__ conf,
                    const float* __restrict__ lmd, const float* __restrict__ priors,
                    const float* __restrict__ gtb, const int* __restrict__ gtl,
                    const float* __restrict__ gtlm, const int* __restrict__ img) {
    __shared__ float4 str[Gn];
    __shared__ float  slm[Gn * 10];
    __shared__ int    slab[Gn];
    __shared__ unsigned sbpi[Gn];
    __shared__ float  wll[8], wlm[8], wpce[8];
    __shared__ int    wnp[8];
    int b = blockIdx.y, tid = threadIdx.x;
    int lane = tid & 31, wid = tid >> 5;
    float w = (float)img[b * 2 + 1];
    float h = (float)img[b * 2 + 0];
    if (tid < Gn * 4)
        ((float*)str)[tid] = gtb[b * Gn * 4 + tid] / ((tid & 1) ? h : w);
    if (tid < Gn * 10 - NTH)
        slm[tid + NTH] = gtlm[b * Gn * 10 + tid + NTH] / (((tid + NTH) & 1) ? h : w);
    slm[tid] = gtlm[b * Gn * 10 + tid] / ((tid & 1) ? h : w);
    if (tid < Gn) {
        int lab = gtl[b * Gn + tid];
        if (lab == 0) lab = 1;
        if (gtlm[b * Gn * 10 + tid * 10] < 0.0f) lab = -1;   // sign preserved by /w
        slab[tid] = lab;
        sbpi[tid] = d_bpi[b * Gn + tid];
    }
    __syncthreads();
    int hv = d_hv[b];
    unsigned long long vm = d_vmask[b];
    unsigned long long cm_all = d_cmask[b * NB3 + blockIdx.x];

    int p = blockIdx.x * NTH + tid;
    float ll = 0.0f, llm = 0.0f, pce = 0.0f;
    int npk = 0;
    if (p < Pn) {
        long long base = (long long)b * Pn + p;
        float2 og = d_povg[base];
        float ov = og.x;
        int bg = __float_as_int(og.y);
        unsigned long long cm = cm_all;
        while (cm) {
            int j = __ffsll((long long)cm) - 1;   // ascending j => later j wins
            cm &= cm - 1;
            if (sbpi[j] == (unsigned)p) {
                bg = j;
                if ((vm >> j) & 1ull) ov = 2.0f;
            }
        }
        int lab = slab[bg];
        int c = (hv && ov >= 0.35f) ? lab : 0;
        bool pos = (c != 0), pos1 = (c > 0);
        float2 cd = ((const float2*)conf)[base];
        float m = fmaxf(cd.x, cd.y);
        float logz = m + logf(expf(cd.x - m) + expf(cd.y - m));
        float ce = logz - (pos ? cd.y : cd.x);
        d_ce[base] = pos ? -1.0f : ce;
        if (pos) {
            npk = 1; pce = ce;
            float4 pr = ((const float4*)priors)[p];
            float4 t = str[bg];
            float s0 = 0.1f * pr.z, s1 = 0.1f * pr.w;
            float tx = ((t.x + t.z) * 0.5f - pr.x) / s0;
            float ty = ((t.y + t.w) * 0.5f - pr.y) / s1;
            float tw = logf((t.z - t.x) / pr.z) / 0.2f;
            float th = logf((t.w - t.y) / pr.w) / 0.2f;
            float4 lc = ((const float4*)loc)[base];
            ll = sl1(lc.x - tx) + sl1(lc.y - ty) + sl1(lc.z - tw) + sl1(lc.w - th);
            if (pos1) {
                npk |= (1 << 16);
                const float2* lrow = (const float2*)(lmd + base * 10);
                const float* tg = &slm[bg * 10];
                #pragma unroll
                for (int i = 0; i < 5; i++) {
                    float2 lv = lrow[i];
                    float ttx = (tg[2*i]   - pr.x) / s0;
                    float tty = (tg[2*i+1] - pr.y) / s1;
                    llm += sl1(lv.x - ttx) + sl1(lv.y - tty);
                }
            }
        }
    }
    #pragma unroll
    for (int off = 16; off > 0; off >>= 1) {
        ll  += __shfl_down_sync(0xFFFFFFFFu, ll,  off);
        llm += __shfl_down_sync(0xFFFFFFFFu, llm, off);
        pce += __shfl_down_sync(0xFFFFFFFFu, pce, off);
        npk += __shfl_down_sync(0xFFFFFFFFu, npk, off);
    }
    if (lane == 0) { wll[wid] = ll; wlm[wid] = llm; wpce[wid] = pce; wnp[wid] = npk; }
    __syncthreads();
    if (tid == 0) {
        float a = 0, c = 0, d = 0; int e = 0;
        #pragma unroll
        for (int i = 0; i < 8; i++) { a += wll[i]; c += wlm[i]; d += wpce[i]; e += wnp[i]; }
        int idx = b * NB3 + blockIdx.x;
        d_part_ll[idx] = a; d_part_lm[idx] = c; d_part_pce[idx] = d; d_part_np[idx] = e;
    }
}

// ---------------- K5: per-batch reduce + radix select, ce in registers ------------
__global__ void __launch_bounds__(NTHB, 1) k_batch() {
    int b = blockIdx.x, tid = threadIdx.x;
    int lane = tid & 31, wid = tid >> 5;
    __shared__ double sdw[32];
    __shared__ int    siw[32];
    __shared__ int    hist[256];
    __shared__ unsigned s_prefix;
    __shared__ int s_rem;
    __shared__ double s_ll, s_lm, s_pce;
    __shared__ int s_np, s_np1;

    double vll = 0, vlm = 0, vpce = 0; int vnp = 0;
    if (tid < NB3) {
        int idx = b * NB3 + tid;
        vll = (double)d_part_ll[idx];
        vlm = (double)d_part_lm[idx];
        vpce = (double)d_part_pce[idx];
        vnp = d_part_np[idx];
    }
    #pragma unroll
    for (int off = 16; off > 0; off >>= 1) {
        vll  += __shfl_down_sync(0xFFFFFFFFu, vll,  off);
        vlm  += __shfl_down_sync(0xFFFFFFFFu, vlm,  off);
        vpce += __shfl_down_sync(0xFFFFFFFFu, vpce, off);
        vnp  += __shfl_down_sync(0xFFFFFFFFu, vnp,  off);
    }
    if (lane == 0) { sdw[wid] = vll; siw[wid] = vnp; }
    __syncthreads();
    if (tid == 0) {
        double a = 0; int e = 0;
        for (int i = 0; i < 32; i++) { a += sdw[i]; e += siw[i]; }
        s_ll = a;
        s_np = e & 0xFFFF; s_np1 = e >> 16;
    }
    __syncthreads();
    if (lane == 0) sdw[wid] = vlm;
    __syncthreads();
    if (tid == 0) { double a = 0; for (int i = 0; i < 32; i++) a += sdw[i]; s_lm = a; }
    __syncthreads();
    if (lane == 0) sdw[wid] = vpce;
    __syncthreads();
    if (tid == 0) { double a = 0; for (int i = 0; i < 32; i++) a += sdw[i]; s_pce = a; }
    if (tid < 256) hist[tid] = 0;
    __syncthreads();

    // read ce ONCE into registers; reuse across all radix passes
    float ce_r[KPT];
    long long base = (long long)b * Pn;
    #pragma unroll
    for (int k = 0; k < KPT; k++) {
        int p = tid + k * NTHB;
        ce_r[k] = (p < Pn) ? d_ce[base + p] : -1.0f;
    }

    int np = s_np;
    int K = min(7 * np, Pn - 1);
    int cntnon = Pn - np;
    double negsum = 0.0;

    if (K > 0) {
        if (K >= cntnon) {
            double locs = 0.0;
            #pragma unroll
            for (int k = 0; k < KPT; k++) if (ce_r[k] >= 0.0f) locs += (double)ce_r[k];
            #pragma unroll
            for (int off = 16; off > 0; off >>= 1) locs += __shfl_down_sync(0xFFFFFFFFu, locs, off);
            if (lane == 0) sdw[wid] = locs;
            __syncthreads();
            if (tid == 0) { double a = 0; for (int i = 0; i < 32; i++) a += sdw[i]; negsum = a; }
        } else {
            if (tid == 0) { s_prefix = 0u; s_rem = K; }
            __syncthreads();
            for (int shift = 24; shift >= 0; shift -= 8) {
                unsigned mask = (shift == 24) ? 0u : (0xFFFFFFFFu << (shift + 8));
                unsigned pref = s_prefix;
                // fixed trip count; OOB/pos = -1 sentinel (warp-uniform collectives)
                #pragma unroll
                for (int k = 0; k < KPT; k++) {
                    float v = ce_r[k];
                    bool valid = false; unsigned bin = 0xFFFFFFFFu;
                    if (v >= 0.0f) {
                        unsigned u = __float_as_uint(v);
                        if ((u & mask) == pref) { valid = true; bin = (u >> shift) & 255u; }
                    }
                    unsigned mm = __match_any_sync(0xFFFFFFFFu, valid ? bin : 0xFFFFFFFFu);
                    if (valid && lane == (__ffs(mm) - 1))
                        atomicAdd(&hist[bin], __popc(mm));
                }
                __syncthreads();
                if (tid == 0) {
                    int rem = s_rem, cum = 0, chosen = 0;
                    for (int v = 255; v >= 0; v--) {
                        int c = hist[v];
                        if (cum + c >= rem) { chosen = v; s_rem = rem - cum; break; }
                        cum += c;
                    }
                    s_prefix = pref | ((unsigned)chosen << shift);
                }
                __syncthreads();
                if (tid < 256) hist[tid] = 0;
                __syncthreads();
            }
            unsigned T = s_prefix;
            int rem = s_rem;
            double locs = 0.0;
            #pragma unroll
            for (int k = 0; k < KPT; k++) {
                float v = ce_r[k];
                if (v >= 0.0f && __float_as_uint(v) > T) locs += (double)v;
            }
            #pragma unroll
            for (int off = 16; off > 0; off >>= 1) locs += __shfl_down_sync(0xFFFFFFFFu, locs, off);
            if (lane == 0) sdw[wid] = locs;
            __syncthreads();
            if (tid == 0) {
                double a = 0; for (int i = 0; i < 32; i++) a += sdw[i];
                negsum = a + (double)rem * (double)__uint_as_float(T);
            }
        }
    }
    if (tid == 0) {
        d_b_ll[b] = s_ll;
        d_b_lm[b] = s_lm;
        d_b_lc[b] = s_pce + negsum;
        d_b_np[b] = np;
        d_b_np1[b] = s_np1;
    }
}

// ---------------- K6: final combine ----------------
__global__ void k_final(float* __restrict__ out) {
    __shared__ double s1[Bn], s2[Bn], s3[Bn];
    __shared__ int i1[Bn], i2[Bn];
    int t = threadIdx.x;
    s1[t] = d_b_ll[t]; s2[t] = d_b_lc[t]; s3[t] = d_b_lm[t];
    i1[t] = d_b_np[t]; i2[t] = d_b_np1[t];
    __syncthreads();
    for (int s = Bn/2; s > 0; s >>= 1) {
        if (t < s) {
            s1[t] += s1[t+s]; s2[t] += s2[t+s]; s3[t] += s3[t+s];
            i1[t] += i1[t+s]; i2[t] += i2[t+s];
        }
        __syncthreads();
    }
    if (t == 0) {
        double N  = (double)(i1[0] > 0 ? i1[0] : 1);
        double N1 = (double)(i2[0] > 0 ? i2[0] : 1);
        out[0] = (float)(s1[0] / N);
        out[1] = (float)(s2[0] / N);
        out[2] = (float)(s3[0] / N1);
    }
}

// ---------------- launcher ----------------
extern "C" void kernel_launch(void* const* d_in, const int* in_sizes, int n_in,
                              void* d_out, int out_size) {
    const float* loc    = (const float*)d_in[0];
    const float* conf   = (const float*)d_in[1];
    const float* lmd    = (const float*)d_in[2];
    const float* priors = (const float*)d_in[3];
    const float* gtb    = (const float*)d_in[4];
    const int*   gtl    = (const int*)d_in[5];
    const float* gtlm   = (const float*)d_in[6];
    const int*   gnum   = (const int*)d_in[7];
    const int*   img    = (const int*)d_in[8];
    float* out = (float*)d_out;

    k_A<<<dim3(NB3, Bn), NTH>>>(gnum, priors, gtb, img);
    k_B<<<(Bn * Gn + NTH - 1) / NTH, NTH>>>(gnum);
    k_C<<<dim3(NB3, Bn), NTH>>>(loc, conf, lmd, priors, gtb, gtl, gtlm, img);
    k_batch<<<Bn, NTHB>>>();
    k_final<<<1, Bn>>>(out);
}